// round 7
// baseline (speedup 1.0000x reference)
#include <cuda_runtime.h>
#include <math.h>

#define BINS 50
#define MBINS (BINS * BINS)                  // 2500
#define JBINS (BINS * BINS * BINS * BINS)    // 6,250,000
#define NBLK 148
#define NTHR 1024
#define GSTRIDE (NBLK * NTHR)

// ---------------- device scratch (no allocations allowed) ----------------
// All state restored to these initial values by the end of every launch.
__device__ double   g_sums[14] = {};
__device__ double   g_entJ = 0.0;
__device__ unsigned g_minq = 0xFFFFFFFFu, g_maxq = 0u;
__device__ unsigned g_minr = 0xFFFFFFFFu, g_maxr = 0u;
__device__ unsigned g_mins = 0xFFFFFFFFu, g_maxs = 0u;
__device__ unsigned g_bar = 0;             // grid-barrier counter (monotonic per launch)
__device__ unsigned g_hist_joint[JBINS];   // 25 MB, starts zero, kept zero
__device__ unsigned g_hist_q[MBINS];
__device__ unsigned g_hist_r[MBINS];

// ---------------- helpers ----------------
__device__ __forceinline__ unsigned fenc(float f) {
    unsigned u = __float_as_uint(f);
    return (u & 0x80000000u) ? ~u : (u | 0x80000000u);
}
__device__ __forceinline__ float fdec(unsigned e) {
    unsigned u = (e & 0x80000000u) ? (e & 0x7fffffffu) : ~e;
    return __uint_as_float(u);
}
__device__ __forceinline__ int binof(float x, float lo, float scale) {
    int i = (int)floorf((x - lo) * scale);
    i = i < 0 ? 0 : i;
    return i > (BINS - 1) ? (BINS - 1) : i;
}

// counter-based grid barrier; all NBLK blocks are co-resident (1 CTA/SM).
__device__ __forceinline__ void grid_barrier(unsigned target) {
    __syncthreads();
    if (threadIdx.x == 0) {
        __threadfence();
        atomicAdd(&g_bar, 1u);
        while (*(volatile unsigned*)&g_bar < target) {}
        __threadfence();
    }
    __syncthreads();
}

__device__ __forceinline__ void transform_row(float4 zv, const float* L, const float* m,
                                              float& s0, float& s1, float& s2, float& s3) {
    s0 = fmaf(zv.x, L[0], m[0]);
    s1 = fmaf(zv.y, L[5],  fmaf(zv.x, L[4],  m[1]));
    s2 = fmaf(zv.z, L[10], fmaf(zv.y, L[9],  fmaf(zv.x, L[8],  m[2])));
    s3 = fmaf(zv.w, L[15], fmaf(zv.z, L[14], fmaf(zv.y, L[13], fmaf(zv.x, L[12], m[3]))));
}

__device__ __forceinline__ double qsum(uint4 v) {
    float a = v.x ? (float)v.x * __logf((float)v.x) : 0.0f;
    float b = v.y ? (float)v.y * __logf((float)v.y) : 0.0f;
    float c = v.z ? (float)v.z * __logf((float)v.z) : 0.0f;
    float d = v.w ? (float)v.w * __logf((float)v.w) : 0.0f;
    return ((double)a + (double)b) + ((double)c + (double)d);
}

// ---------------- the one persistent kernel ----------------
__global__ void __launch_bounds__(NTHR, 1)
k_all(const float2* __restrict__ q, const float2* __restrict__ r,
      const float4* __restrict__ z, float* __restrict__ out, int n, int S) {
    __shared__ double   shd[32][14];
    __shared__ unsigned shm[32][4];
    __shared__ float    sChol[16];
    __shared__ float    sMean[4];
    __shared__ unsigned shq[MBINS];
    __shared__ unsigned shr[MBINS];

    const int tid = threadIdx.x;
    const int wid = tid >> 5, lane = tid & 31;
    const int gid = blockIdx.x * NTHR + tid;
    const unsigned FULL = 0xFFFFFFFFu;

    // ================= phase 0: moments + min/max of q and r =================
    {
        double s[14];
#pragma unroll
        for (int k = 0; k < 14; k++) s[k] = 0.0;
        unsigned mnq = 0xFFFFFFFFu, mxq = 0u, mnr = 0xFFFFFFFFu, mxr = 0u;

        for (int i = gid; i < n; i += GSTRIDE) {
            float2 qv = q[i];
            float2 rv = r[i];
            double x0 = qv.x, x1 = qv.y, x2 = rv.x, x3 = rv.y;
            s[0] += x0; s[1] += x1; s[2] += x2; s[3] += x3;
            s[4]  += x0 * x0; s[5]  += x0 * x1; s[6]  += x0 * x2; s[7]  += x0 * x3;
            s[8]  += x1 * x1; s[9]  += x1 * x2; s[10] += x1 * x3;
            s[11] += x2 * x2; s[12] += x2 * x3; s[13] += x3 * x3;
            unsigned e;
            e = fenc(qv.x); mnq = min(mnq, e); mxq = max(mxq, e);
            e = fenc(qv.y); mnq = min(mnq, e); mxq = max(mxq, e);
            e = fenc(rv.x); mnr = min(mnr, e); mxr = max(mxr, e);
            e = fenc(rv.y); mnr = min(mnr, e); mxr = max(mxr, e);
        }
#pragma unroll
        for (int k = 0; k < 14; k++)
            for (int off = 16; off; off >>= 1) s[k] += __shfl_down_sync(FULL, s[k], off);
        for (int off = 16; off; off >>= 1) {
            mnq = min(mnq, __shfl_down_sync(FULL, mnq, off));
            mxq = max(mxq, __shfl_down_sync(FULL, mxq, off));
            mnr = min(mnr, __shfl_down_sync(FULL, mnr, off));
            mxr = max(mxr, __shfl_down_sync(FULL, mxr, off));
        }
        if (lane == 0) {
#pragma unroll
            for (int k = 0; k < 14; k++) shd[wid][k] = s[k];
            shm[wid][0] = mnq; shm[wid][1] = mxq; shm[wid][2] = mnr; shm[wid][3] = mxr;
        }
        __syncthreads();
        if (tid == 0) {
            for (int w = 1; w < 32; w++) {
#pragma unroll
                for (int k = 0; k < 14; k++) shd[0][k] += shd[w][k];
                shm[0][0] = min(shm[0][0], shm[w][0]);
                shm[0][1] = max(shm[0][1], shm[w][1]);
                shm[0][2] = min(shm[0][2], shm[w][2]);
                shm[0][3] = max(shm[0][3], shm[w][3]);
            }
#pragma unroll
            for (int k = 0; k < 14; k++) atomicAdd(&g_sums[k], shd[0][k]);
            atomicMin(&g_minq, shm[0][0]); atomicMax(&g_maxq, shm[0][1]);
            atomicMin(&g_minr, shm[0][2]); atomicMax(&g_maxr, shm[0][3]);
        }
    }

    grid_barrier(1 * NBLK);

    // ============ phase 1: per-block cholesky, marginal hists, sample min/max ============
    if (tid == 0) {
        double shs[14];
#pragma unroll
        for (int k = 0; k < 14; k++) shs[k] = g_sums[k];
        double nn = (double)n;
        double mean[4];
#pragma unroll
        for (int i = 0; i < 4; i++) mean[i] = shs[i] / nn;
        float cov[4][4];
        int ix = 4;
#pragma unroll
        for (int i = 0; i < 4; i++)
#pragma unroll
            for (int j = i; j < 4; j++) {
                float c = (float)((shs[ix++] - nn * mean[i] * mean[j]) / (nn - 1.0));
                cov[i][j] = c; cov[j][i] = c;
            }
#pragma unroll
        for (int i = 0; i < 4; i++) cov[i][i] += 1e-6f;
        float L[4][4] = {};
#pragma unroll
        for (int j = 0; j < 4; j++) {
            float d = cov[j][j];
#pragma unroll
            for (int k = 0; k < 4; k++) if (k < j) d -= L[j][k] * L[j][k];
            float dj = sqrtf(d);
            L[j][j] = dj;
            float inv = __frcp_rn(dj);
#pragma unroll
            for (int i = 0; i < 4; i++) if (i > j) {
                float v = cov[i][j];
#pragma unroll
                for (int k = 0; k < 4; k++) if (k < j) v -= L[i][k] * L[j][k];
                L[i][j] = v * inv;
            }
        }
#pragma unroll
        for (int i = 0; i < 4; i++) {
            sMean[i] = (float)mean[i];
#pragma unroll
            for (int j = 0; j < 4; j++) sChol[i * 4 + j] = L[i][j];
        }
    }
    // zero shared marginal hists while thread 0 does cholesky
    for (int i = tid; i < MBINS; i += NTHR) { shq[i] = 0u; shr[i] = 0u; }
    __syncthreads();

    {   // marginal histograms (block-private smem, flush with atomics)
        float loq = fdec(g_minq), hiq = fdec(g_maxq);
        float lor = fdec(g_minr), hir = fdec(g_maxr);
        float sq = (float)BINS / (hiq - loq);
        float sr = (float)BINS / (hir - lor);
        for (int i = gid; i < n; i += GSTRIDE) {
            float2 qv = q[i];
            atomicAdd(&shq[binof(qv.x, loq, sq) * BINS + binof(qv.y, loq, sq)], 1u);
            float2 rv = r[i];
            atomicAdd(&shr[binof(rv.x, lor, sr) * BINS + binof(rv.y, lor, sr)], 1u);
        }
        __syncthreads();
        for (int i = tid; i < MBINS; i += NTHR) {
            unsigned a = shq[i]; if (a) atomicAdd(&g_hist_q[i], a);
            unsigned b = shr[i]; if (b) atomicAdd(&g_hist_r[i], b);
        }
    }

    {   // transform + global min/max of samples (batched loads)
        float L[16], m[4];
#pragma unroll
        for (int i = 0; i < 16; i++) L[i] = sChol[i];
#pragma unroll
        for (int i = 0; i < 4; i++) m[i] = sMean[i];

        unsigned mn = 0xFFFFFFFFu, mx = 0u;
        int i = gid;
        for (; i + 3 * GSTRIDE < S; i += 4 * GSTRIDE) {
            float4 a = z[i];
            float4 b = z[i + GSTRIDE];
            float4 c = z[i + 2 * GSTRIDE];
            float4 d = z[i + 3 * GSTRIDE];
            float s0, s1, s2, s3;
            unsigned e;
            transform_row(a, L, m, s0, s1, s2, s3);
            e = fenc(s0); mn = min(mn, e); mx = max(mx, e);
            e = fenc(s1); mn = min(mn, e); mx = max(mx, e);
            e = fenc(s2); mn = min(mn, e); mx = max(mx, e);
            e = fenc(s3); mn = min(mn, e); mx = max(mx, e);
            transform_row(b, L, m, s0, s1, s2, s3);
            e = fenc(s0); mn = min(mn, e); mx = max(mx, e);
            e = fenc(s1); mn = min(mn, e); mx = max(mx, e);
            e = fenc(s2); mn = min(mn, e); mx = max(mx, e);
            e = fenc(s3); mn = min(mn, e); mx = max(mx, e);
            transform_row(c, L, m, s0, s1, s2, s3);
            e = fenc(s0); mn = min(mn, e); mx = max(mx, e);
            e = fenc(s1); mn = min(mn, e); mx = max(mx, e);
            e = fenc(s2); mn = min(mn, e); mx = max(mx, e);
            e = fenc(s3); mn = min(mn, e); mx = max(mx, e);
            transform_row(d, L, m, s0, s1, s2, s3);
            e = fenc(s0); mn = min(mn, e); mx = max(mx, e);
            e = fenc(s1); mn = min(mn, e); mx = max(mx, e);
            e = fenc(s2); mn = min(mn, e); mx = max(mx, e);
            e = fenc(s3); mn = min(mn, e); mx = max(mx, e);
        }
        for (; i < S; i += GSTRIDE) {
            float s0, s1, s2, s3;
            transform_row(z[i], L, m, s0, s1, s2, s3);
            unsigned e;
            e = fenc(s0); mn = min(mn, e); mx = max(mx, e);
            e = fenc(s1); mn = min(mn, e); mx = max(mx, e);
            e = fenc(s2); mn = min(mn, e); mx = max(mx, e);
            e = fenc(s3); mn = min(mn, e); mx = max(mx, e);
        }
        for (int off = 16; off; off >>= 1) {
            mn = min(mn, __shfl_down_sync(FULL, mn, off));
            mx = max(mx, __shfl_down_sync(FULL, mx, off));
        }
        if (lane == 0) { shm[wid][0] = mn; shm[wid][1] = mx; }
        __syncthreads();
        if (tid == 0) {
            for (int w = 1; w < 32; w++) {
                mn = min(mn, shm[w][0]);
                mx = max(mx, shm[w][1]);
            }
            atomicMin(&g_mins, mn);
            atomicMax(&g_maxs, mx);
        }
    }

    grid_barrier(2 * NBLK);

    // ================= phase 2: joint histogram (z is L2-hot now) =================
    {
        float L[16], m[4];
#pragma unroll
        for (int i = 0; i < 16; i++) L[i] = sChol[i];
#pragma unroll
        for (int i = 0; i < 4; i++) m[i] = sMean[i];
        float lo = fdec(g_mins), hi = fdec(g_maxs);
        float sc = (float)BINS / (hi - lo);

        int i = gid;
        for (; i + 3 * GSTRIDE < S; i += 4 * GSTRIDE) {
            float4 a = z[i];
            float4 b = z[i + GSTRIDE];
            float4 c = z[i + 2 * GSTRIDE];
            float4 d = z[i + 3 * GSTRIDE];
            float s0, s1, s2, s3;
            transform_row(a, L, m, s0, s1, s2, s3);
            int fa = ((binof(s0, lo, sc) * BINS + binof(s1, lo, sc)) * BINS +
                      binof(s2, lo, sc)) * BINS + binof(s3, lo, sc);
            transform_row(b, L, m, s0, s1, s2, s3);
            int fb = ((binof(s0, lo, sc) * BINS + binof(s1, lo, sc)) * BINS +
                      binof(s2, lo, sc)) * BINS + binof(s3, lo, sc);
            transform_row(c, L, m, s0, s1, s2, s3);
            int fc = ((binof(s0, lo, sc) * BINS + binof(s1, lo, sc)) * BINS +
                      binof(s2, lo, sc)) * BINS + binof(s3, lo, sc);
            transform_row(d, L, m, s0, s1, s2, s3);
            int fd = ((binof(s0, lo, sc) * BINS + binof(s1, lo, sc)) * BINS +
                      binof(s2, lo, sc)) * BINS + binof(s3, lo, sc);
            atomicAdd(&g_hist_joint[fa], 1u);
            atomicAdd(&g_hist_joint[fb], 1u);
            atomicAdd(&g_hist_joint[fc], 1u);
            atomicAdd(&g_hist_joint[fd], 1u);
        }
        for (; i < S; i += GSTRIDE) {
            float s0, s1, s2, s3;
            transform_row(z[i], L, m, s0, s1, s2, s3);
            int f = ((binof(s0, lo, sc) * BINS + binof(s1, lo, sc)) * BINS +
                     binof(s2, lo, sc)) * BINS + binof(s3, lo, sc);
            atomicAdd(&g_hist_joint[f], 1u);
        }
    }

    grid_barrier(3 * NBLK);

    // ================= phase 3: joint entropy scan + clear-on-read =================
    {
        double s0 = 0.0, s1 = 0.0, s2 = 0.0, s3 = 0.0;
        uint4* p = (uint4*)g_hist_joint;
        const uint4 zero = make_uint4(0u, 0u, 0u, 0u);
        const int Q = JBINS / 4;
        int i = gid;
        for (; i + 3 * GSTRIDE < Q; i += 4 * GSTRIDE) {
            uint4 a = p[i];
            uint4 b = p[i + GSTRIDE];
            uint4 c = p[i + 2 * GSTRIDE];
            uint4 d = p[i + 3 * GSTRIDE];
            if (a.x | a.y | a.z | a.w) { s0 += qsum(a); p[i] = zero; }
            if (b.x | b.y | b.z | b.w) { s1 += qsum(b); p[i + GSTRIDE] = zero; }
            if (c.x | c.y | c.z | c.w) { s2 += qsum(c); p[i + 2 * GSTRIDE] = zero; }
            if (d.x | d.y | d.z | d.w) { s3 += qsum(d); p[i + 3 * GSTRIDE] = zero; }
        }
        for (; i < Q; i += GSTRIDE) {
            uint4 v = p[i];
            if (v.x | v.y | v.z | v.w) { s0 += qsum(v); p[i] = zero; }
        }
        double sum = (s0 + s1) + (s2 + s3);
        for (int off = 16; off; off >>= 1) sum += __shfl_down_sync(FULL, sum, off);
        if (lane == 0) shd[wid][0] = sum;
        __syncthreads();
        if (tid == 0) {
            for (int w = 1; w < 32; w++) sum += shd[w][0];
            atomicAdd(&g_entJ, sum);
        }
    }

    grid_barrier(4 * NBLK);

    // ================= phase 4: block 0 finalizes + resets state =================
    if (blockIdx.x != 0) return;
    {
        double sq = 0.0, sr = 0.0;
        for (int i = tid; i < MBINS; i += NTHR) {
            unsigned a = g_hist_q[i]; if (a) { sq += (double)a * (double)__logf((float)a); g_hist_q[i] = 0u; }
            unsigned b = g_hist_r[i]; if (b) { sr += (double)b * (double)__logf((float)b); g_hist_r[i] = 0u; }
        }
        for (int off = 16; off; off >>= 1) {
            sq += __shfl_down_sync(FULL, sq, off);
            sr += __shfl_down_sync(FULL, sr, off);
        }
        if (lane == 0) { shd[wid][0] = sq; shd[wid][1] = sr; }
        __syncthreads();
        if (tid == 0) {
            for (int w = 1; w < 32; w++) { sq += shd[w][0]; sr += shd[w][1]; }
            double nn = (double)n, SS = (double)S;
            double H_T = log(nn) - sq / nn;
            double H_I = log(nn) - sr / nn;
            double H_J = log(SS) - g_entJ / SS;
            double v = H_J / (H_T + H_I);
            v = v < 0.0 ? 0.0 : (v > 1.0 ? 1.0 : v);
            out[0] = (float)v;

            // restore scalar state for the next replay
            g_entJ = 0.0;
#pragma unroll
            for (int k = 0; k < 14; k++) g_sums[k] = 0.0;
            g_minq = 0xFFFFFFFFu; g_maxq = 0u;
            g_minr = 0xFFFFFFFFu; g_maxr = 0u;
            g_mins = 0xFFFFFFFFu; g_maxs = 0u;
            g_bar = 0u;
        }
    }
}

// ---------------- launch ----------------
extern "C" void kernel_launch(void* const* d_in, const int* in_sizes, int n_in,
                              void* d_out, int out_size) {
    const float* q = (const float*)d_in[0];
    const float* r = (const float*)d_in[1];
    const float* z = (const float*)d_in[2];
    int n = in_sizes[0] / 2;   // 200000 rows of D=2
    int S = in_sizes[2] / 4;   // 2000000 rows of 2D=4

    k_all<<<NBLK, NTHR>>>((const float2*)q, (const float2*)r,
                          (const float4*)z, (float*)d_out, n, S);
}

// round 8
// speedup vs baseline: 1.2621x; 1.2621x over previous
#include <cuda_runtime.h>
#include <math.h>

#define BINS 50
#define MBINS (BINS * BINS)                  // 2500
#define JBINS (BINS * BINS * BINS * BINS)    // 6,250,000

// ---------------- device scratch (no allocations allowed) ----------------
// All state is restored to these initial values at the end of every
// kernel_launch execution (clear-on-read), so each graph replay is identical.
__device__ double   g_sums[14] = {};   // 0..3 sum x_i ; 4..13 upper-tri sum x_i x_j
__device__ double   g_entJ = 0.0;      // sum c*log(c) over joint hist
__device__ unsigned g_minq = 0xFFFFFFFFu, g_maxq = 0u;
__device__ unsigned g_minr = 0xFFFFFFFFu, g_maxr = 0u;
__device__ unsigned g_mins = 0xFFFFFFFFu, g_maxs = 0u;
__device__ float    g_L[16];           // lower-tri cholesky factor (row major)
__device__ float    g_mean[4];
__device__ unsigned g_hist_joint[JBINS];   // 25 MB, starts zero, kept zero
__device__ unsigned g_hist_q[MBINS];
__device__ unsigned g_hist_r[MBINS];

// ---------------- helpers ----------------
__device__ __forceinline__ unsigned fenc(float f) {
    unsigned u = __float_as_uint(f);
    return (u & 0x80000000u) ? ~u : (u | 0x80000000u);
}
__device__ __forceinline__ float fdec(unsigned e) {
    unsigned u = (e & 0x80000000u) ? (e & 0x7fffffffu) : ~e;
    return __uint_as_float(u);
}
__device__ __forceinline__ int binof(float x, float lo, float scale) {
    int i = (int)floorf((x - lo) * scale);
    i = i < 0 ? 0 : i;
    return i > (BINS - 1) ? (BINS - 1) : i;
}

// ---------------- kernels (bodies identical to the 90.7us baseline; ----------------
// ---------------- only PDL trigger/sync prologues added)             ----------------

// moments + per-array min/max of q and r
__global__ void __launch_bounds__(256) k_stats(const float2* __restrict__ q,
                                               const float2* __restrict__ r, int n) {
    cudaTriggerProgrammaticLaunchCompletion();
    int idx = blockIdx.x * blockDim.x + threadIdx.x;
    int stride = gridDim.x * blockDim.x;
    double s[14];
#pragma unroll
    for (int k = 0; k < 14; k++) s[k] = 0.0;
    unsigned mnq = 0xFFFFFFFFu, mxq = 0u, mnr = 0xFFFFFFFFu, mxr = 0u;

    for (int i = idx; i < n; i += stride) {
        float2 qv = q[i];
        float2 rv = r[i];
        double x0 = qv.x, x1 = qv.y, x2 = rv.x, x3 = rv.y;
        s[0] += x0; s[1] += x1; s[2] += x2; s[3] += x3;
        s[4]  += x0 * x0; s[5]  += x0 * x1; s[6]  += x0 * x2; s[7]  += x0 * x3;
        s[8]  += x1 * x1; s[9]  += x1 * x2; s[10] += x1 * x3;
        s[11] += x2 * x2; s[12] += x2 * x3; s[13] += x3 * x3;
        unsigned e;
        e = fenc(qv.x); mnq = min(mnq, e); mxq = max(mxq, e);
        e = fenc(qv.y); mnq = min(mnq, e); mxq = max(mxq, e);
        e = fenc(rv.x); mnr = min(mnr, e); mxr = max(mxr, e);
        e = fenc(rv.y); mnr = min(mnr, e); mxr = max(mxr, e);
    }

    const unsigned FULL = 0xFFFFFFFFu;
#pragma unroll
    for (int k = 0; k < 14; k++)
        for (int off = 16; off; off >>= 1) s[k] += __shfl_down_sync(FULL, s[k], off);
    for (int off = 16; off; off >>= 1) {
        mnq = min(mnq, __shfl_down_sync(FULL, mnq, off));
        mxq = max(mxq, __shfl_down_sync(FULL, mxq, off));
        mnr = min(mnr, __shfl_down_sync(FULL, mnr, off));
        mxr = max(mxr, __shfl_down_sync(FULL, mxr, off));
    }

    __shared__ double   sh[8][14];
    __shared__ unsigned shm[8][4];
    int wid = threadIdx.x >> 5, lane = threadIdx.x & 31;
    if (lane == 0) {
#pragma unroll
        for (int k = 0; k < 14; k++) sh[wid][k] = s[k];
        shm[wid][0] = mnq; shm[wid][1] = mxq; shm[wid][2] = mnr; shm[wid][3] = mxr;
    }
    __syncthreads();
    if (threadIdx.x == 0) {
        int nw = blockDim.x >> 5;
        for (int w = 1; w < nw; w++) {
#pragma unroll
            for (int k = 0; k < 14; k++) sh[0][k] += sh[w][k];
            shm[0][0] = min(shm[0][0], shm[w][0]);
            shm[0][1] = max(shm[0][1], shm[w][1]);
            shm[0][2] = min(shm[0][2], shm[w][2]);
            shm[0][3] = max(shm[0][3], shm[w][3]);
        }
#pragma unroll
        for (int k = 0; k < 14; k++) atomicAdd(&g_sums[k], sh[0][k]);
        atomicMin(&g_minq, shm[0][0]); atomicMax(&g_maxq, shm[0][1]);
        atomicMin(&g_minr, shm[0][2]); atomicMax(&g_maxr, shm[0][3]);
    }
}

// mean, covariance (+eps*I), 4x4 cholesky — fp32 factorization
__global__ void k_finalize(int n) {
    cudaTriggerProgrammaticLaunchCompletion();
    cudaGridDependencySynchronize();
    __shared__ double shs[14];
    int t = threadIdx.x;
    if (t < 14) shs[t] = g_sums[t];
    __syncthreads();
    if (t != 0) return;

    double nn = (double)n;
    double mean[4];
#pragma unroll
    for (int i = 0; i < 4; i++) mean[i] = shs[i] / nn;
    float cov[4][4];
    int idx = 4;
#pragma unroll
    for (int i = 0; i < 4; i++)
#pragma unroll
        for (int j = i; j < 4; j++) {
            float c = (float)((shs[idx++] - nn * mean[i] * mean[j]) / (nn - 1.0));
            cov[i][j] = c; cov[j][i] = c;
        }
#pragma unroll
    for (int i = 0; i < 4; i++) cov[i][i] += 1e-6f;

    float L[4][4] = {};
#pragma unroll
    for (int j = 0; j < 4; j++) {
        float d = cov[j][j];
#pragma unroll
        for (int k = 0; k < 4; k++) if (k < j) d -= L[j][k] * L[j][k];
        float dj = sqrtf(d);
        L[j][j] = dj;
        float inv = __frcp_rn(dj);
#pragma unroll
        for (int i = 0; i < 4; i++) if (i > j) {
            float v = cov[i][j];
#pragma unroll
            for (int k = 0; k < 4; k++) if (k < j) v -= L[i][k] * L[j][k];
            L[i][j] = v * inv;
        }
    }
#pragma unroll
    for (int i = 0; i < 4; i++) {
        g_mean[i] = (float)mean[i];
#pragma unroll
        for (int j = 0; j < 4; j++) g_L[i * 4 + j] = L[i][j];
    }
}

// marginal histograms for q and r (shared-memory privatized)
__global__ void __launch_bounds__(256) k_margHist(const float2* __restrict__ q,
                                                  const float2* __restrict__ r, int n) {
    cudaTriggerProgrammaticLaunchCompletion();
    __shared__ unsigned shq[MBINS];
    __shared__ unsigned shr[MBINS];
    for (int i = threadIdx.x; i < MBINS; i += blockDim.x) { shq[i] = 0u; shr[i] = 0u; }
    cudaGridDependencySynchronize();
    __syncthreads();

    float loq = fdec(g_minq), hiq = fdec(g_maxq);
    float lor = fdec(g_minr), hir = fdec(g_maxr);
    float sq = (float)BINS / (hiq - loq);
    float sr = (float)BINS / (hir - lor);

    int idx = blockIdx.x * blockDim.x + threadIdx.x;
    int stride = gridDim.x * blockDim.x;
    for (int i = idx; i < n; i += stride) {
        float2 qv = q[i];
        atomicAdd(&shq[binof(qv.x, loq, sq) * BINS + binof(qv.y, loq, sq)], 1u);
        float2 rv = r[i];
        atomicAdd(&shr[binof(rv.x, lor, sr) * BINS + binof(rv.y, lor, sr)], 1u);
    }
    __syncthreads();
    for (int i = threadIdx.x; i < MBINS; i += blockDim.x) {
        unsigned a = shq[i]; if (a) atomicAdd(&g_hist_q[i], a);
        unsigned b = shr[i]; if (b) atomicAdd(&g_hist_r[i], b);
    }
}

__device__ __forceinline__ void transform_row(float4 zv, const float* L, const float* m,
                                              float& s0, float& s1, float& s2, float& s3) {
    s0 = fmaf(zv.x, L[0], m[0]);
    s1 = fmaf(zv.y, L[5],  fmaf(zv.x, L[4],  m[1]));
    s2 = fmaf(zv.z, L[10], fmaf(zv.y, L[9],  fmaf(zv.x, L[8],  m[2])));
    s3 = fmaf(zv.w, L[15], fmaf(zv.z, L[14], fmaf(zv.y, L[13], fmaf(zv.x, L[12], m[3]))));
}

// pass 1 over z: global min/max of the transformed samples
__global__ void __launch_bounds__(256) k_tmm(const float4* __restrict__ z, int S) {
    cudaTriggerProgrammaticLaunchCompletion();
    cudaGridDependencySynchronize();
    float L[16], m[4];
#pragma unroll
    for (int i = 0; i < 16; i++) L[i] = g_L[i];
#pragma unroll
    for (int i = 0; i < 4; i++) m[i] = g_mean[i];

    unsigned mn = 0xFFFFFFFFu, mx = 0u;
    int idx = blockIdx.x * blockDim.x + threadIdx.x;
    int stride = gridDim.x * blockDim.x;
    for (int i = idx; i < S; i += stride) {
        float s0, s1, s2, s3;
        transform_row(z[i], L, m, s0, s1, s2, s3);
        unsigned e;
        e = fenc(s0); mn = min(mn, e); mx = max(mx, e);
        e = fenc(s1); mn = min(mn, e); mx = max(mx, e);
        e = fenc(s2); mn = min(mn, e); mx = max(mx, e);
        e = fenc(s3); mn = min(mn, e); mx = max(mx, e);
    }
    const unsigned FULL = 0xFFFFFFFFu;
    for (int off = 16; off; off >>= 1) {
        mn = min(mn, __shfl_down_sync(FULL, mn, off));
        mx = max(mx, __shfl_down_sync(FULL, mx, off));
    }
    __shared__ unsigned shmn[8], shmx[8];
    int wid = threadIdx.x >> 5, lane = threadIdx.x & 31;
    if (lane == 0) { shmn[wid] = mn; shmx[wid] = mx; }
    __syncthreads();
    if (threadIdx.x == 0) {
        int nw = blockDim.x >> 5;
        for (int w = 1; w < nw; w++) { mn = min(mn, shmn[w]); mx = max(mx, shmx[w]); }
        atomicMin(&g_mins, mn);
        atomicMax(&g_maxs, mx);
    }
}

// pass 2 over z: recompute transform, bin into the joint histogram
__global__ void __launch_bounds__(256) k_jhist(const float4* __restrict__ z, int S) {
    cudaTriggerProgrammaticLaunchCompletion();
    cudaGridDependencySynchronize();
    float L[16], m[4];
#pragma unroll
    for (int i = 0; i < 16; i++) L[i] = g_L[i];
#pragma unroll
    for (int i = 0; i < 4; i++) m[i] = g_mean[i];
    float lo = fdec(g_mins), hi = fdec(g_maxs);
    float sc = (float)BINS / (hi - lo);

    int idx = blockIdx.x * blockDim.x + threadIdx.x;
    int stride = gridDim.x * blockDim.x;
    for (int i = idx; i < S; i += stride) {
        float s0, s1, s2, s3;
        transform_row(z[i], L, m, s0, s1, s2, s3);
        int i0 = binof(s0, lo, sc);
        int i1 = binof(s1, lo, sc);
        int i2 = binof(s2, lo, sc);
        int i3 = binof(s3, lo, sc);
        int flat = ((i0 * BINS + i1) * BINS + i2) * BINS + i3;
        atomicAdd(&g_hist_joint[flat], 1u);
    }
}

// sum c*log(c) over joint histogram; clear-on-read (restore zeros for next replay)
__global__ void __launch_bounds__(256) k_entJ() {
    cudaTriggerProgrammaticLaunchCompletion();
    cudaGridDependencySynchronize();
    double sum = 0.0;
    uint4* p = (uint4*)g_hist_joint;
    const uint4 zero = make_uint4(0u, 0u, 0u, 0u);
    int idx = blockIdx.x * blockDim.x + threadIdx.x;
    int stride = gridDim.x * blockDim.x;
    for (int i = idx; i < JBINS / 4; i += stride) {
        uint4 v = p[i];
        if (v.x | v.y | v.z | v.w) {
            if (v.x) sum += (double)v.x * (double)logf((float)v.x);
            if (v.y) sum += (double)v.y * (double)logf((float)v.y);
            if (v.z) sum += (double)v.z * (double)logf((float)v.z);
            if (v.w) sum += (double)v.w * (double)logf((float)v.w);
            p[i] = zero;
        }
    }
    const unsigned FULL = 0xFFFFFFFFu;
    for (int off = 16; off; off >>= 1) sum += __shfl_down_sync(FULL, sum, off);
    __shared__ double sh[8];
    int wid = threadIdx.x >> 5, lane = threadIdx.x & 31;
    if (lane == 0) sh[wid] = sum;
    __syncthreads();
    if (threadIdx.x == 0) {
        int nw = blockDim.x >> 5;
        for (int w = 1; w < nw; w++) sum += sh[w];
        atomicAdd(&g_entJ, sum);
    }
}

// marginal entropies + final scalar; restores ALL device state for next replay
__global__ void __launch_bounds__(512) k_final(float* out, int n, int S) {
    cudaGridDependencySynchronize();
    double sq = 0.0, sr = 0.0;
    for (int i = threadIdx.x; i < MBINS; i += blockDim.x) {
        unsigned a = g_hist_q[i]; if (a) { sq += (double)a * (double)logf((float)a); g_hist_q[i] = 0u; }
        unsigned b = g_hist_r[i]; if (b) { sr += (double)b * (double)logf((float)b); g_hist_r[i] = 0u; }
    }
    const unsigned FULL = 0xFFFFFFFFu;
    for (int off = 16; off; off >>= 1) {
        sq += __shfl_down_sync(FULL, sq, off);
        sr += __shfl_down_sync(FULL, sr, off);
    }
    __shared__ double shq[16], shr[16];
    int wid = threadIdx.x >> 5, lane = threadIdx.x & 31;
    if (lane == 0) { shq[wid] = sq; shr[wid] = sr; }
    __syncthreads();
    if (threadIdx.x == 0) {
        int nw = blockDim.x >> 5;
        for (int w = 1; w < nw; w++) { sq += shq[w]; sr += shr[w]; }
        double nn = (double)n, SS = (double)S;
        double H_T = log(nn) - sq / nn;
        double H_I = log(nn) - sr / nn;
        double H_J = log(SS) - g_entJ / SS;
        double v = H_J / (H_T + H_I);
        v = v < 0.0 ? 0.0 : (v > 1.0 ? 1.0 : v);
        out[0] = (float)v;

        // restore scalar state for the next replay
        g_entJ = 0.0;
#pragma unroll
        for (int k = 0; k < 14; k++) g_sums[k] = 0.0;
        g_minq = 0xFFFFFFFFu; g_maxq = 0u;
        g_minr = 0xFFFFFFFFu; g_maxr = 0u;
        g_mins = 0xFFFFFFFFu; g_maxs = 0u;
    }
}

// ---------------- launch (PDL chain on one stream) ----------------
static inline void launch_pdl(void* fn, dim3 grid, dim3 block, void** args, bool pdl) {
    cudaLaunchConfig_t cfg = {};
    cfg.gridDim = grid;
    cfg.blockDim = block;
    cfg.dynamicSmemBytes = 0;
    cfg.stream = 0;
    cudaLaunchAttribute attr[1];
    if (pdl) {
        attr[0].id = cudaLaunchAttributeProgrammaticStreamSerialization;
        attr[0].val.programmaticStreamSerializationAllowed = 1;
        cfg.attrs = attr;
        cfg.numAttrs = 1;
    }
    cudaLaunchKernelExC(&cfg, fn, args);
}

extern "C" void kernel_launch(void* const* d_in, const int* in_sizes, int n_in,
                              void* d_out, int out_size) {
    const float2* q = (const float2*)d_in[0];
    const float2* r = (const float2*)d_in[1];
    const float4* z = (const float4*)d_in[2];
    float* out = (float*)d_out;
    int n = in_sizes[0] / 2;   // 200000 rows of D=2
    int S = in_sizes[2] / 4;   // 2000000 rows of 2D=4

    {   void* a[] = { (void*)&q, (void*)&r, (void*)&n };
        launch_pdl((void*)k_stats, dim3(296), dim3(256), a, false); }
    {   void* a[] = { (void*)&n };
        launch_pdl((void*)k_finalize, dim3(1), dim3(32), a, true); }
    {   void* a[] = { (void*)&q, (void*)&r, (void*)&n };
        launch_pdl((void*)k_margHist, dim3(64), dim3(256), a, true); }
    {   void* a[] = { (void*)&z, (void*)&S };
        launch_pdl((void*)k_tmm, dim3(1184), dim3(256), a, true); }
    {   void* a[] = { (void*)&z, (void*)&S };
        launch_pdl((void*)k_jhist, dim3(1184), dim3(256), a, true); }
    {   void* a[] = {};
        launch_pdl((void*)k_entJ, dim3(1184), dim3(256), a, true); }
    {   void* a[] = { (void*)&out, (void*)&n, (void*)&S };
        launch_pdl((void*)k_final, dim3(1), dim3(512), a, true); }
}